// round 16
// baseline (speedup 1.0000x reference)
#include <cuda_runtime.h>
#include <cuda_bf16.h>
#include <math.h>
#include <stdint.h>

#define B_    8
#define T_    12
#define N_    1536
#define H_    64
#define TH_   768
#define HID2_ 128
#define TOUT_ 12
#define M_    (B_*N_)          // 12288
#define DELTA_   0.5f
#define ALPHA_   0.3f
#define KHOPS_   3.0f
#define KL_EPS_  1e-10f
#define BN_EPS_  1e-5f
#define DEG_MIN_ 1e-6f

typedef unsigned long long u64;

// ---------------- warp mma.sync bf16 + helpers ----------------
__device__ __forceinline__ void mma_bf16(float* c,
    uint32_t a0, uint32_t a1, uint32_t a2, uint32_t a3,
    uint32_t b0, uint32_t b1)
{
    asm volatile(
        "mma.sync.aligned.m16n8k16.row.col.f32.bf16.bf16.f32 "
        "{%0,%1,%2,%3}, {%4,%5,%6,%7}, {%8,%9}, {%0,%1,%2,%3};"
        : "+f"(c[0]), "+f"(c[1]), "+f"(c[2]), "+f"(c[3])
        : "r"(a0), "r"(a1), "r"(a2), "r"(a3), "r"(b0), "r"(b1));
}
__device__ __forceinline__ void ldsm_x4(uint32_t& r0, uint32_t& r1,
                                        uint32_t& r2, uint32_t& r3, uint32_t addr)
{
    asm volatile("ldmatrix.sync.aligned.m8n8.x4.shared.b16 {%0,%1,%2,%3}, [%4];"
        : "=r"(r0), "=r"(r1), "=r"(r2), "=r"(r3) : "r"(addr));
}
__device__ __forceinline__ uint32_t s2u(const void* p) {
    uint32_t a;
    asm("{ .reg .u64 t; cvta.to.shared.u64 t, %1; cvt.u32.u64 %0, t; }" : "=r"(a) : "l"(p));
    return a;
}
__device__ __forceinline__ void split_bf16(float v, __nv_bfloat16& h, __nv_bfloat16& l) {
    h = __float2bfloat16(v);
    l = __float2bfloat16(v - __bfloat162float(h));
}
__device__ __forceinline__ uint32_t mpack(bool m0, bool m1) {
    return (m0 ? 0x3F80u : 0u) | (m1 ? 0x3F800000u : 0u);
}
__device__ __forceinline__ void cp_async8(uint32_t saddr, const void* gaddr) {
    asm volatile("cp.async.ca.shared.global [%0], [%1], 8;" :: "r"(saddr), "l"(gaddr));
}
// split a pair to packed hi and lo bf16x2
__device__ __forceinline__ void hil(float a, float b, uint32_t& ph, uint32_t& pl) {
    __nv_bfloat16 ha = __float2bfloat16(a), hb = __float2bfloat16(b);
    __nv_bfloat16 la = __float2bfloat16(a - __bfloat162float(ha));
    __nv_bfloat16 lb = __float2bfloat16(b - __bfloat162float(hb));
    __nv_bfloat162 vh{ha, hb}, vl{la, lb};
    ph = *(uint32_t*)&vh;
    pl = *(uint32_t*)&vl;
}

#define KPCH 40
#define KP   24
#define XP   136

// k_pair_mma pipeline buffers
#define BUF_U16  15360
#define BUF_B    (BUF_U16*2)
#define PIPE3_B  (3*BUF_B)

// bf16x3 ldmatrix inner step over one 32-k smem tile (A 128 rows, B 64 rows)
__device__ __forceinline__ void mma_tile(float acc[8][4],
    uint32_t aAh, uint32_t aAl, uint32_t aBh, uint32_t aBl,
    int laneA_off, int laneB_off)
{
#pragma unroll
    for (int ks = 0; ks < 2; ks++) {
        uint32_t ah[4], al[4];
        ldsm_x4(ah[0],ah[1],ah[2],ah[3], aAh + laneA_off + ks*32);
        ldsm_x4(al[0],al[1],al[2],al[3], aAl + laneA_off + ks*32);
#pragma unroll
        for (int t2 = 0; t2 < 4; t2++) {
            uint32_t bh[4], bl[4];
            ldsm_x4(bh[0],bh[1],bh[2],bh[3], aBh + laneB_off + t2*(16*KPCH*2) + ks*32);
            ldsm_x4(bl[0],bl[1],bl[2],bl[3], aBl + laneB_off + t2*(16*KPCH*2) + ks*32);
            mma_bf16(acc[2*t2],   ah[0],ah[1],ah[2],ah[3], bh[0],bh[1]);
            mma_bf16(acc[2*t2],   ah[0],ah[1],ah[2],ah[3], bl[0],bl[1]);
            mma_bf16(acc[2*t2],   al[0],al[1],al[2],al[3], bh[0],bh[1]);
            mma_bf16(acc[2*t2+1], ah[0],ah[1],ah[2],ah[3], bh[2],bh[3]);
            mma_bf16(acc[2*t2+1], ah[0],ah[1],ah[2],ah[3], bl[2],bl[3]);
            mma_bf16(acc[2*t2+1], al[0],al[1],al[2],al[3], bh[2],bh[3]);
        }
    }
}

__device__ __forceinline__ void cp_fill(uint32_t sbase,
    const __nv_bfloat16* __restrict__ gh, const __nv_bfloat16* __restrict__ gl,
    const __nv_bfloat16* __restrict__ wh, const __nv_bfloat16* __restrict__ wl,
    int m0, int n0, int KD, int k0, int tid)
{
#pragma unroll
    for (int q = 0; q < 4; q++) {
        int idx = q*256 + tid;
        int r = idx >> 3, c = (idx & 7) * 4;
        cp_async8(sbase + (r*KPCH + c)*2,          gh + (size_t)(m0+r)*KD + k0 + c);
        cp_async8(sbase + (5120 + r*KPCH + c)*2,   gl + (size_t)(m0+r)*KD + k0 + c);
    }
#pragma unroll
    for (int q = 0; q < 2; q++) {
        int idx = q*256 + tid;
        int r = idx >> 3, c = (idx & 7) * 4;
        cp_async8(sbase + (10240 + r*KPCH + c)*2,  wh + (size_t)(n0+r)*KD + k0 + c);
        cp_async8(sbase + (12800 + r*KPCH + c)*2,  wl + (size_t)(n0+r)*KD + k0 + c);
    }
    asm volatile("cp.async.commit_group;" ::: "memory");
}

__device__ __forceinline__ void pipe_loop(float acc[8][4], uint32_t dbase,
    const __nv_bfloat16* __restrict__ Ahp, const __nv_bfloat16* __restrict__ Alp,
    const __nv_bfloat16* __restrict__ Bhp, const __nv_bfloat16* __restrict__ Blp,
    int m0, int n0, int KD, int NITER, int tid, int laneA_off, int laneB_off)
{
    cp_fill(dbase, Ahp, Alp, Bhp, Blp, m0, n0, KD, 0, tid);
    if (NITER > 1)
        cp_fill(dbase + BUF_B, Ahp, Alp, Bhp, Blp, m0, n0, KD, 32, tid);
    int bufsel = 0;
    for (int it = 0; it < NITER; it++) {
        if (it + 2 <= NITER)
            asm volatile("cp.async.wait_group 1;" ::: "memory");
        else
            asm volatile("cp.async.wait_group 0;" ::: "memory");
        __syncthreads();
        uint32_t sb = dbase + bufsel * BUF_B;
        mma_tile(acc, sb, sb + 5120*2, sb + 10240*2, sb + 12800*2, laneA_off, laneB_off);
        if (it + 2 < NITER) {
            int nb = bufsel + 2; if (nb >= 3) nb -= 3;
            cp_fill(dbase + nb * BUF_B, Ahp, Alp, Bhp, Blp, m0, n0, KD, (it+2)*32, tid);
        }
        bufsel++; if (bufsel == 3) bufsel = 0;
    }
}

// ---------------- device scratch ----------------
__device__ float g_s  [M_];
__device__ float g_deg[M_];
__device__ float g_ind[M_];
__device__ __align__(16) float g_af[M_*T_];
__device__ __align__(16) float g_ab[M_*T_];
__device__ __align__(16) __nv_bfloat16 g_pbh[(size_t)M_*16];
__device__ __align__(16) __nv_bfloat16 g_pbl[(size_t)M_*16];
__device__ __align__(16) __nv_bfloat16 g_lbh[(size_t)M_*16];
__device__ __align__(16) __nv_bfloat16 g_lbl[(size_t)M_*16];
__device__ __align__(16) __nv_bfloat16 g_zh[(size_t)M_*TH_];
__device__ __align__(16) __nv_bfloat16 g_zl[(size_t)M_*TH_];
__device__ __align__(16) __nv_bfloat16 g_wh[(size_t)(HID2_+H_)*TH_];
__device__ __align__(16) __nv_bfloat16 g_wl[(size_t)(HID2_+H_)*TH_];
__device__ __align__(16) __nv_bfloat16 g_cwh[49152];
__device__ __align__(16) __nv_bfloat16 g_cwl[49152];
__device__ __align__(16) __nv_bfloat16 g_h1h[(size_t)M_*HID2_];
__device__ __align__(16) __nv_bfloat16 g_h1l[(size_t)M_*HID2_];
__device__ __align__(16) float g_zp[(size_t)M_*H_];

// ---------------- K1: fused softmax + weight prep ----------------
__global__ void __launch_bounds__(256) k_softprep(
    const float* __restrict__ x,
    const float* __restrict__ w1, const float* __restrict__ proj,
    const float* __restrict__ w2, const float* __restrict__ w3,
    const float* __restrict__ dw1, const float* __restrict__ dw2)
{
    int idx = blockIdx.x * 256 + threadIdx.x;

    if (idx < M_) {
        int bn = idx;
        int b = bn / N_, n = bn % N_;
        float v[T_];
        float mx = -1e30f;
#pragma unroll
        for (int t = 0; t < T_; t++) {
            v[t] = x[((size_t)(b*T_ + t))*N_ + n];
            mx = fmaxf(mx, v[t]);
        }
        float sum = 0.f;
#pragma unroll
        for (int t = 0; t < T_; t++) { v[t] = expf(v[t] - mx); sum += v[t]; }
        float inv = 1.f / sum;
        float s = 0.f;
        size_t b16 = (size_t)bn * 16;
        size_t b12 = (size_t)bn * T_;
#pragma unroll
        for (int t = 0; t < T_; t++) {
            float p  = v[t] * inv;
            float lp = logf(p + KL_EPS_);
            __nv_bfloat16 ph, pl, lh, ll;
            split_bf16(p,  ph, pl);
            split_bf16(lp, lh, ll);
            g_pbh[b16 + t] = ph;  g_pbl[b16 + t] = pl;
            g_lbh[b16 + t] = lh;  g_lbl[b16 + t] = ll;
            g_af[b12 + t] = 0.f;
            g_ab[b12 + t] = 0.f;
            s = fmaf(p, lp, s);
        }
#pragma unroll
        for (int t = T_; t < 16; t++) {
            g_pbh[b16 + t] = __float2bfloat16(0.f);
            g_pbl[b16 + t] = __float2bfloat16(0.f);
            g_lbh[b16 + t] = __float2bfloat16(0.f);
            g_lbl[b16 + t] = __float2bfloat16(0.f);
        }
        g_s[bn] = s;
        g_deg[bn] = 0.f;
        g_ind[bn] = 0.f;
    }

    if (idx < (HID2_+H_)*TH_) {
        int n = idx / TH_, k = idx % TH_;
        float v = (n < HID2_) ? w1[(size_t)k*HID2_ + n] : proj[(size_t)k*H_ + (n - HID2_)];
        __nv_bfloat16 h, l;
        split_bf16(v, h, l);
        g_wh[idx] = h;
        g_wl[idx] = l;
        return;
    }
    int c = idx - (HID2_+H_)*TH_;
    if (c >= 49152) return;
    float v;
    if (c < 16384)      { int j = c;         int n = j/128, k = j%128; v = w2 [(size_t)k*HID2_ + n]; }
    else if (c < 24576) { int j = c - 16384; int n = j/128, k = j%128; v = w3 [(size_t)k*H_    + n]; }
    else if (c < 32768) { int j = c - 24576; int n = j/64,  k = j%64;  v = dw1[(size_t)k*HID2_ + n]; }
    else                { int j = c - 32768; int n = j/128, k = j%128; v = dw2[(size_t)k*HID2_ + n]; }
    __nv_bfloat16 h, l;
    split_bf16(v, h, l);
    g_cwh[c] = h;
    g_cwl[c] = l;
}

// ---------------- K2: graph via tensor cores (frozen) ----------------
#define SG_PIH 0
#define SG_PIL 3072
#define SG_PJH 6144
#define SG_PJL 9216
#define SG_LIH 12288
#define SG_LIL 15360
#define SG_LJH 18432
#define SG_LJL 21504
#define SG_XH  24576
#define SG_XL  (24576+2176)
#define SG_M   (24576+4352)
#define SG_TOT (SG_M + 128*XP)
#define SG_BYTES (SG_TOT*2)

__global__ void __launch_bounds__(256) k_graph_mma(const float* __restrict__ x) {
    extern __shared__ __align__(16) __nv_bfloat16 sm[];
    __shared__ float ssi[128], ssj[128];

    const int tid  = threadIdx.x;
    const int w    = tid >> 5, lane = tid & 31;
    const int b    = blockIdx.z;
    const int i0   = blockIdx.x * 128;
    const int j0   = blockIdx.y * 128;
    const int bN   = b * N_;

#pragma unroll
    for (int q = 0; q < 4; q++) {
        int idx = q*256 + tid;
        int a = idx >> 7, r = idx & 127;
        const __nv_bfloat16* src;
        __nv_bfloat16* dst;
        switch (a) {
            case 0: src = g_pbh + (size_t)(bN+i0+r)*16; dst = sm + SG_PIH + r*KP; break;
            case 1: src = g_pbl + (size_t)(bN+i0+r)*16; dst = sm + SG_PIL + r*KP; break;
            case 2: src = g_pbh + (size_t)(bN+j0+r)*16; dst = sm + SG_PJH + r*KP; break;
            case 3: src = g_pbl + (size_t)(bN+j0+r)*16; dst = sm + SG_PJL + r*KP; break;
            case 4: src = g_lbh + (size_t)(bN+i0+r)*16; dst = sm + SG_LIH + r*KP; break;
            case 5: src = g_lbl + (size_t)(bN+i0+r)*16; dst = sm + SG_LIL + r*KP; break;
            case 6: src = g_lbh + (size_t)(bN+j0+r)*16; dst = sm + SG_LJH + r*KP; break;
            default:src = g_lbl + (size_t)(bN+j0+r)*16; dst = sm + SG_LJL + r*KP; break;
        }
        *(uint4*)dst       = *(const uint4*)src;
        *(uint4*)(dst + 8) = *(const uint4*)(src + 8);
    }
#pragma unroll
    for (int q = 0; q < 8; q++) {
        int idx = q*256 + tid;
        int t = idx >> 7, j = idx & 127;
        float v = (t < T_) ? x[((size_t)(b*T_ + t))*N_ + j0 + j] : (t == 12 ? 1.f : 0.f);
        __nv_bfloat16 h, l;
        split_bf16(v, h, l);
        sm[SG_XH + t*XP + j] = h;
        sm[SG_XL + t*XP + j] = l;
    }
    if (tid < 128) ssi[tid] = g_s[bN + i0 + tid];
    else           ssj[tid-128] = g_s[bN + j0 + tid - 128];
    __syncthreads();

    const int r0   = w*16 + (lane >> 2);
    const int koff = (lane & 3) * 2;
    __nv_bfloat16* Mm = sm + SG_M;
    const __nv_bfloat16* Xh = sm + SG_XH;
    const __nv_bfloat16* Xl = sm + SG_XL;

    float acc[16][4];

    // ===== Phase A =====
    {
#pragma unroll
        for (int nt = 0; nt < 16; nt++)
#pragma unroll
            for (int q = 0; q < 4; q++) acc[nt][q] = 0.f;
        uint32_t ah0 = *(const uint32_t*)&sm[SG_PIH + r0*KP + koff];
        uint32_t ah1 = *(const uint32_t*)&sm[SG_PIH + (r0+8)*KP + koff];
        uint32_t ah2 = *(const uint32_t*)&sm[SG_PIH + r0*KP + koff + 8];
        uint32_t ah3 = *(const uint32_t*)&sm[SG_PIH + (r0+8)*KP + koff + 8];
        uint32_t al0 = *(const uint32_t*)&sm[SG_PIL + r0*KP + koff];
        uint32_t al1 = *(const uint32_t*)&sm[SG_PIL + (r0+8)*KP + koff];
        uint32_t al2 = *(const uint32_t*)&sm[SG_PIL + r0*KP + koff + 8];
        uint32_t al3 = *(const uint32_t*)&sm[SG_PIL + (r0+8)*KP + koff + 8];
#pragma unroll
        for (int nt = 0; nt < 16; nt++) {
            int br = nt*8 + (lane >> 2);
            uint32_t bh0 = *(const uint32_t*)&sm[SG_LJH + br*KP + koff];
            uint32_t bh1 = *(const uint32_t*)&sm[SG_LJH + br*KP + koff + 8];
            uint32_t bl0 = *(const uint32_t*)&sm[SG_LJL + br*KP + koff];
            uint32_t bl1 = *(const uint32_t*)&sm[SG_LJL + br*KP + koff + 8];
            mma_bf16(acc[nt], ah0,ah1,ah2,ah3, bh0,bh1);
            mma_bf16(acc[nt], ah0,ah1,ah2,ah3, bl0,bl1);
            mma_bf16(acc[nt], al0,al1,al2,al3, bh0,bh1);
        }
        float si0 = ssi[r0], si1 = ssi[r0+8];
#pragma unroll
        for (int nt = 0; nt < 16; nt++) {
            *(uint32_t*)&Mm[r0*XP + nt*8 + koff] =
                mpack((si0 - acc[nt][0]) < DELTA_, (si0 - acc[nt][1]) < DELTA_);
            *(uint32_t*)&Mm[(r0+8)*XP + nt*8 + koff] =
                mpack((si1 - acc[nt][2]) < DELTA_, (si1 - acc[nt][3]) < DELTA_);
        }
        __syncwarp();
        float acc2[2][4];
#pragma unroll
        for (int nt = 0; nt < 2; nt++)
#pragma unroll
            for (int q = 0; q < 4; q++) acc2[nt][q] = 0.f;
#pragma unroll
        for (int kk = 0; kk < 8; kk++) {
            uint32_t a0 = *(const uint32_t*)&Mm[r0*XP + kk*16 + koff];
            uint32_t a1 = *(const uint32_t*)&Mm[(r0+8)*XP + kk*16 + koff];
            uint32_t a2 = *(const uint32_t*)&Mm[r0*XP + kk*16 + koff + 8];
            uint32_t a3 = *(const uint32_t*)&Mm[(r0+8)*XP + kk*16 + koff + 8];
#pragma unroll
            for (int nt = 0; nt < 2; nt++) {
                int br = nt*8 + (lane >> 2);
                uint32_t xh0 = *(const uint32_t*)&Xh[br*XP + kk*16 + koff];
                uint32_t xh1 = *(const uint32_t*)&Xh[br*XP + kk*16 + koff + 8];
                uint32_t xl0 = *(const uint32_t*)&Xl[br*XP + kk*16 + koff];
                uint32_t xl1 = *(const uint32_t*)&Xl[br*XP + kk*16 + koff + 8];
                mma_bf16(acc2[nt], a0,a1,a2,a3, xh0,xh1);
                mma_bf16(acc2[nt], a0,a1,a2,a3, xl0,xl1);
            }
        }
        int gi0 = bN + i0 + r0;
#pragma unroll
        for (int nt = 0; nt < 2; nt++) {
            int c0 = nt*8 + koff;
#pragma unroll
            for (int q = 0; q < 4; q++) {
                int cc = c0 + (q & 1);
                int gi = gi0 + (q >> 1) * 8;
                if (cc < T_)       atomicAdd(&g_af[(size_t)gi*T_ + cc], acc2[nt][q]);
                else if (cc == 12) atomicAdd(&g_deg[gi], acc2[nt][q]);
            }
        }
    }

    // ===== Phase B =====
    {
#pragma unroll
        for (int nt = 0; nt < 16; nt++)
#pragma unroll
            for (int q = 0; q < 4; q++) acc[nt][q] = 0.f;
        uint32_t ah0 = *(const uint32_t*)&sm[SG_PJH + r0*KP + koff];
        uint32_t ah1 = *(const uint32_t*)&sm[SG_PJH + (r0+8)*KP + koff];
        uint32_t ah2 = *(const uint32_t*)&sm[SG_PJH + r0*KP + koff + 8];
        uint32_t ah3 = *(const uint32_t*)&sm[SG_PJH + (r0+8)*KP + koff + 8];
        uint32_t al0 = *(const uint32_t*)&sm[SG_PJL + r0*KP + koff];
        uint32_t al1 = *(const uint32_t*)&sm[SG_PJL + (r0+8)*KP + koff];
        uint32_t al2 = *(const uint32_t*)&sm[SG_PJL + r0*KP + koff + 8];
        uint32_t al3 = *(const uint32_t*)&sm[SG_PJL + (r0+8)*KP + koff + 8];
#pragma unroll
        for (int nt = 0; nt < 16; nt++) {
            int br = nt*8 + (lane >> 2);
            uint32_t bh0 = *(const uint32_t*)&sm[SG_LIH + br*KP + koff];
            uint32_t bh1 = *(const uint32_t*)&sm[SG_LIH + br*KP + koff + 8];
            uint32_t bl0 = *(const uint32_t*)&sm[SG_LIL + br*KP + koff];
            uint32_t bl1 = *(const uint32_t*)&sm[SG_LIL + br*KP + koff + 8];
            mma_bf16(acc[nt], ah0,ah1,ah2,ah3, bh0,bh1);
            mma_bf16(acc[nt], ah0,ah1,ah2,ah3, bl0,bl1);
            mma_bf16(acc[nt], al0,al1,al2,al3, bh0,bh1);
        }
        __syncthreads();
        float sj0 = ssj[r0], sj1 = ssj[r0+8];
        const __nv_bfloat16 one = __float2bfloat16(1.f);
        const __nv_bfloat16 zro = __float2bfloat16(0.f);
#pragma unroll
        for (int nt = 0; nt < 16; nt++) {
            int ci = nt*8 + koff;
            Mm[(ci    )*XP + r0    ] = ((sj0 - acc[nt][0]) < DELTA_) ? one : zro;
            Mm[(ci + 1)*XP + r0    ] = ((sj0 - acc[nt][1]) < DELTA_) ? one : zro;
            Mm[(ci    )*XP + r0 + 8] = ((sj1 - acc[nt][2]) < DELTA_) ? one : zro;
            Mm[(ci + 1)*XP + r0 + 8] = ((sj1 - acc[nt][3]) < DELTA_) ? one : zro;
        }
        __syncthreads();
        float acc2[2][4];
#pragma unroll
        for (int nt = 0; nt < 2; nt++)
#pragma unroll
            for (int q = 0; q < 4; q++) acc2[nt][q] = 0.f;
#pragma unroll
        for (int kk = 0; kk < 8; kk++) {
            uint32_t a0 = *(const uint32_t*)&Mm[r0*XP + kk*16 + koff];
            uint32_t a1 = *(const uint32_t*)&Mm[(r0+8)*XP + kk*16 + koff];
            uint32_t a2 = *(const uint32_t*)&Mm[r0*XP + kk*16 + koff + 8];
            uint32_t a3 = *(const uint32_t*)&Mm[(r0+8)*XP + kk*16 + koff + 8];
#pragma unroll
            for (int nt = 0; nt < 2; nt++) {
                int br = nt*8 + (lane >> 2);
                uint32_t xh0 = *(const uint32_t*)&Xh[br*XP + kk*16 + koff];
                uint32_t xh1 = *(const uint32_t*)&Xh[br*XP + kk*16 + koff + 8];
                uint32_t xl0 = *(const uint32_t*)&Xl[br*XP + kk*16 + koff];
                uint32_t xl1 = *(const uint32_t*)&Xl[br*XP + kk*16 + koff + 8];
                mma_bf16(acc2[nt], a0,a1,a2,a3, xh0,xh1);
                mma_bf16(acc2[nt], a0,a1,a2,a3, xl0,xl1);
            }
        }
        int gi0 = bN + i0 + r0;
#pragma unroll
        for (int nt = 0; nt < 2; nt++) {
            int c0 = nt*8 + koff;
#pragma unroll
            for (int q = 0; q < 4; q++) {
                int cc = c0 + (q & 1);
                int gi = gi0 + (q >> 1) * 8;
                if (cc < T_)       atomicAdd(&g_ab[(size_t)gi*T_ + cc], acc2[nt][q]);
                else if (cc == 12) atomicAdd(&g_ind[gi], acc2[nt][q]);
            }
        }
    }
}

// ---------------- K3: build z (gfin fused: gg computed inline) ----------------
__global__ void __launch_bounds__(256) k_buildz(const float* __restrict__ x,
                                                const float* __restrict__ W1,
                                                const float* __restrict__ W2) {
    int idx8 = blockIdx.x * 256 + threadIdx.x;
    if (idx8 >= M_*TH_/8) return;
    int row = idx8 / (TH_/8);
    int c8  = idx8 % (TH_/8);
    int t   = c8 >> 3;
    int h8  = (c8 & 7) * 8;
    int b = row / N_, n = row % N_;
    float xv = x[((size_t)(b*T_ + t))*N_ + n];
    // fused gfin
    float rf = (KHOPS_ * ALPHA_)        * __frcp_rn(fmaxf(__ldg(&g_deg[row]), DEG_MIN_));
    float rb = (KHOPS_ * (1.f-ALPHA_))  * __frcp_rn(fmaxf(__ldg(&g_ind[row]), DEG_MIN_));
    float gg = rf * __ldg(&g_af[(size_t)row*T_ + t]) + rb * __ldg(&g_ab[(size_t)row*T_ + t]);
    float4 w1a = *(const float4*)&W1[h8];
    float4 w1b = *(const float4*)&W1[h8 + 4];
    float4 w2a = *(const float4*)&W2[h8];
    float4 w2b = *(const float4*)&W2[h8 + 4];
    float v[8];
    v[0] = fmaxf(fmaf(xv, w1a.x, gg * w2a.x), 0.f);
    v[1] = fmaxf(fmaf(xv, w1a.y, gg * w2a.y), 0.f);
    v[2] = fmaxf(fmaf(xv, w1a.z, gg * w2a.z), 0.f);
    v[3] = fmaxf(fmaf(xv, w1a.w, gg * w2a.w), 0.f);
    v[4] = fmaxf(fmaf(xv, w1b.x, gg * w2b.x), 0.f);
    v[5] = fmaxf(fmaf(xv, w1b.y, gg * w2b.y), 0.f);
    v[6] = fmaxf(fmaf(xv, w1b.z, gg * w2b.z), 0.f);
    v[7] = fmaxf(fmaf(xv, w1b.w, gg * w2b.w), 0.f);
    uint4 oh, ol;
#pragma unroll
    for (int q = 0; q < 8; q += 2) {
        uint32_t ph, pl;
        hil(v[q], v[q+1], ph, pl);
        ((uint32_t*)&oh)[q>>1] = ph;
        ((uint32_t*)&ol)[q>>1] = pl;
    }
    size_t o = (size_t)idx8 * 8;
    *(uint4*)&g_zh[o] = oh;
    *(uint4*)&g_zl[o] = ol;
}

// ---------------- K4: pipelined bf16x3 fused GEMM: h1(hi/lo)=relu(Z@w1+b1), zp=Z@proj ----------------
__global__ void __launch_bounds__(256) k_pair_mma(const float* __restrict__ b1v) {
    extern __shared__ __align__(16) __nv_bfloat16 dsm[];
    const int tid  = threadIdx.x;
    const int w    = tid >> 5, lane = tid & 31;
    const int m0   = blockIdx.x * 128;
    const int n0   = blockIdx.y * 64;

    float acc[8][4];
#pragma unroll
    for (int t = 0; t < 8; t++)
#pragma unroll
        for (int j = 0; j < 4; j++) acc[t][j] = 0.f;

    const uint32_t dbase = s2u(dsm);
    const int laneA_off = ((w*16 + (lane & 15))*KPCH)*2 + ((lane>>4)&1)*16;
    const int laneB_off = (((lane & 7) + ((lane>>4)&1)*8)*KPCH)*2 + ((lane>>3)&1)*16;

    pipe_loop(acc, dbase, g_zh, g_zl, g_wh, g_wl, m0, n0, TH_, TH_/32, tid,
              laneA_off, laneB_off);

    const int m  = m0 + w*16 + (lane >> 2);
    const int cl = (lane & 3) * 2;
    if (n0 < HID2_) {
#pragma unroll
        for (int t = 0; t < 8; t++) {
            int col = n0 + t*8 + cl;
            float b0 = __ldg(&b1v[col]), b1 = __ldg(&b1v[col+1]);
            float v00 = fmaxf(acc[t][0] + b0, 0.f), v01 = fmaxf(acc[t][1] + b1, 0.f);
            float v10 = fmaxf(acc[t][2] + b0, 0.f), v11 = fmaxf(acc[t][3] + b1, 0.f);
            uint32_t ph0, pl0, ph1, pl1;
            hil(v00, v01, ph0, pl0);
            hil(v10, v11, ph1, pl1);
            *(uint32_t*)&g_h1h[(size_t)m*HID2_ + col]     = ph0;
            *(uint32_t*)&g_h1l[(size_t)m*HID2_ + col]     = pl0;
            *(uint32_t*)&g_h1h[(size_t)(m+8)*HID2_ + col] = ph1;
            *(uint32_t*)&g_h1l[(size_t)(m+8)*HID2_ + col] = pl1;
        }
    } else {
#pragma unroll
        for (int t = 0; t < 8; t++) {
            int col = t*8 + cl;
            *(float2*)&g_zp[(size_t)m*H_ + col]     = make_float2(acc[t][0], acc[t][1]);
            *(float2*)&g_zp[(size_t)(m+8)*H_ + col] = make_float2(acc[t][2], acc[t][3]);
        }
    }
}

// ---------------- K5: fused register-chained MLP tail + final stage ----------------
#define CCHA 5120
#define CSA_L 20480
#define CSB   40960
#define CSB_L 61440
#define CHAIN_BYTES (81920*2)           // 163840 B dynamic smem
#define ES_OFF   0
#define ES_P     68
#define H4_OFF   34816
#define H4_P     132
#define W3S_OFF  102400
#define PJS_OFF  108544

__device__ __forceinline__ void chain_fillB(__nv_bfloat16* cs,
    const __nv_bfloat16* __restrict__ wh, const __nv_bfloat16* __restrict__ wl,
    int NR, int KD, int tid)
{
    for (int i = tid; i < NR*KD/4; i += 256) {
        int r  = i / (KD/4);
        int k4 = (i % (KD/4)) * 4;
        int off = (k4 >> 5)*CCHA + r*KPCH + (k4 & 31);
        *(uint2*)&cs[CSB   + off] = *(const uint2*)&wh[(size_t)r*KD + k4];
        *(uint2*)&cs[CSB_L + off] = *(const uint2*)&wl[(size_t)r*KD + k4];
    }
}

template<int NK16, int NNT2>
__device__ __forceinline__ void chain_mma(float (*acc)[4],
    const uint32_t (*ah)[4], const uint32_t (*al)[4],
    uint32_t aB, uint32_t aBL, int laneB_off)
{
#pragma unroll
    for (int kg = 0; kg < NK16; kg++) {
        uint32_t addr  = aB  + (kg>>1)*(CCHA*2) + laneB_off + (kg&1)*32;
        uint32_t addrl = aBL + (kg>>1)*(CCHA*2) + laneB_off + (kg&1)*32;
#pragma unroll
        for (int t2 = 0; t2 < NNT2; t2++) {
            uint32_t bh[4], bl[4];
            ldsm_x4(bh[0],bh[1],bh[2],bh[3], addr  + t2*(16*KPCH*2));
            ldsm_x4(bl[0],bl[1],bl[2],bl[3], addrl + t2*(16*KPCH*2));
            mma_bf16(acc[2*t2],   ah[kg][0],ah[kg][1],ah[kg][2],ah[kg][3], bh[0],bh[1]);
            mma_bf16(acc[2*t2],   ah[kg][0],ah[kg][1],ah[kg][2],ah[kg][3], bl[0],bl[1]);
            mma_bf16(acc[2*t2],   al[kg][0],al[kg][1],al[kg][2],al[kg][3], bh[0],bh[1]);
            mma_bf16(acc[2*t2+1], ah[kg][0],ah[kg][1],ah[kg][2],ah[kg][3], bh[2],bh[3]);
            mma_bf16(acc[2*t2+1], ah[kg][0],ah[kg][1],ah[kg][2],ah[kg][3], bl[2],bl[3]);
            mma_bf16(acc[2*t2+1], al[kg][0],al[kg][1],al[kg][2],al[kg][3], bh[2],bh[3]);
        }
    }
}

template<int NK16>
__device__ __forceinline__ void chain_conv(const float (*acc)[4],
    uint32_t (*ah)[4], uint32_t (*al)[4])
{
#pragma unroll
    for (int kg = 0; kg < NK16; kg++) {
        hil(acc[2*kg][0],   acc[2*kg][1],   ah[kg][0], al[kg][0]);
        hil(acc[2*kg][2],   acc[2*kg][3],   ah[kg][1], al[kg][1]);
        hil(acc[2*kg+1][0], acc[2*kg+1][1], ah[kg][2], al[kg][2]);
        hil(acc[2*kg+1][2], acc[2*kg+1][3], ah[kg][3], al[kg][3]);
    }
}

__global__ void __launch_bounds__(256) k_chain(
    const float* __restrict__ b2,  const float* __restrict__ b3,
    const float* __restrict__ bng, const float* __restrict__ bnb,
    const float* __restrict__ bnm, const float* __restrict__ bnv,
    const float* __restrict__ db1, const float* __restrict__ db2,
    const float* __restrict__ dw3, const float* __restrict__ db3,
    const float* __restrict__ dpj,
    const float* __restrict__ dbng, const float* __restrict__ dbnb,
    const float* __restrict__ dbnm, const float* __restrict__ dbnv,
    float* __restrict__ out)
{
    extern __shared__ __align__(16) __nv_bfloat16 cs[];
    const int tid  = threadIdx.x;
    const int w    = tid >> 5, lane = tid & 31;
    const int m0   = blockIdx.x * 128;
    const int mr   = w*16 + (lane >> 2);
    const int m    = m0 + mr;
    const int cl   = (lane & 3) * 2;
    const uint32_t csb = s2u(cs);
    const int laneA_off = ((w*16 + (lane & 15))*KPCH)*2 + ((lane>>4)&1)*16;
    const int laneB_off = (((lane & 7) + ((lane>>4)&1)*8)*KPCH)*2 + ((lane>>3)&1)*16;
    const uint32_t aB = csb + CSB*2, aBL = csb + CSB_L*2;
    float* Es  = (float*)((char*)cs + ES_OFF);
    float* H4s = (float*)((char*)cs + H4_OFF);
    float* w3s = (float*)((char*)cs + W3S_OFF);
    float* pjs = (float*)((char*)cs + PJS_OFF);

    uint32_t ah[8][4], al[8][4];
    float acc[16][4];

    for (int i = tid; i < 128*128/4; i += 256) {
        int r  = i >> 5;
        int k4 = (i & 31) * 4;
        int off = (k4 >> 5)*CCHA + r*KPCH + (k4 & 31);
        *(uint2*)&cs[off]         = *(const uint2*)&g_h1h[(size_t)(m0+r)*HID2_ + k4];
        *(uint2*)&cs[CSA_L + off] = *(const uint2*)&g_h1l[(size_t)(m0+r)*HID2_ + k4];
    }
    chain_fillB(cs, g_cwh, g_cwl, 128, 128, tid);
    __syncthreads();

#pragma unroll
    for (int kg = 0; kg < 8; kg++) {
        ldsm_x4(ah[kg][0],ah[kg][1],ah[kg][2],ah[kg][3],
                csb + (kg>>1)*(CCHA*2) + laneA_off + (kg&1)*32);
        ldsm_x4(al[kg][0],al[kg][1],al[kg][2],al[kg][3],
                csb + CSA_L*2 + (kg>>1)*(CCHA*2) + laneA_off + (kg&1)*32);
    }
    __syncthreads();

    // ===== stage 1: h2 = relu(h1 @ w2 + b2) =====
#pragma unroll
    for (int nt = 0; nt < 16; nt++)
#pragma unroll
        for (int q = 0; q < 4; q++) acc[nt][q] = 0.f;
    chain_mma<8,8>(acc, ah, al, aB, aBL, laneB_off);
#pragma unroll
    for (int nt = 0; nt < 16; nt++) {
        int col = nt*8 + cl;
        float c0 = __ldg(&b2[col]), c1 = __ldg(&b2[col+1]);
        acc[nt][0] = fmaxf(acc[nt][0] + c0, 0.f);
        acc[nt][1] = fmaxf(acc[nt][1] + c1, 0.f);
        acc[nt][2] = fmaxf(acc[nt][2] + c0, 0.f);
        acc[nt][3] = fmaxf(acc[nt][3] + c1, 0.f);
    }
    chain_conv<8>(acc, ah, al);

    // ===== stage 2: e = BN(h2 @ w3 + b3 + zp) -> Es =====
    __syncthreads();
    chain_fillB(cs, g_cwh + 16384, g_cwl + 16384, 64, 128, tid);
    __syncthreads();
#pragma unroll
    for (int nt = 0; nt < 8; nt++)
#pragma unroll
        for (int q = 0; q < 4; q++) acc[nt][q] = 0.f;
    chain_mma<8,4>(acc, ah, al, aB, aBL, laneB_off);
#pragma unroll
    for (int nt = 0; nt < 8; nt++) {
        int col = nt*8 + cl;
        float c0 = __ldg(&b3[col]), c1 = __ldg(&b3[col+1]);
        float v0 = acc[nt][0] + c0 + g_zp[(size_t)m*H_ + col];
        float v1 = acc[nt][1] + c1 + g_zp[(size_t)m*H_ + col + 1];
        float v2 = acc[nt][2] + c0 + g_zp[(size_t)(m+8)*H_ + col];
        float v3 = acc[nt][3] + c1 + g_zp[(size_t)(m+8)*H_ + col + 1];
        float s0 = rsqrtf(__ldg(&bnv[col])   + BN_EPS_) * __ldg(&bng[col]);
        float s1 = rsqrtf(__ldg(&bnv[col+1]) + BN_EPS_) * __ldg(&bng[col+1]);
        float m0v = __ldg(&bnm[col]), m1v = __ldg(&bnm[col+1]);
        float a0 = __ldg(&bnb[col]),  a1 = __ldg(&bnb[col+1]);
        v0 = (v0 - m0v) * s0 + a0;
        v1 = (v1 - m1v) * s1 + a1;
        v2 = (v2 - m0v) * s0 + a0;
        v3 = (v3 - m1v) * s1 + a1;
        Es[mr*ES_P + col]     = v0;
        Es[mr*ES_P + col + 1] = v1;
        Es[(mr+8)*ES_P + col]     = v2;
        Es[(mr+8)*ES_P + col + 1] = v3;
        acc[nt][0] = v0; acc[nt][1] = v1; acc[nt][2] = v2; acc[nt][3] = v3;
    }
    chain_conv<4>(acc, ah, al);

    // ===== stage 3: h3 = relu(e @ dw1 + db1) =====
    __syncthreads();
    chain_fillB(cs, g_cwh + 24576, g_cwl + 24576, 128, 64, tid);
    __syncthreads();
#pragma unroll
    for (int nt = 0; nt < 16; nt++)
#pragma unroll
        for (int q = 0; q < 4; q++) acc[nt][q] = 0.f;
    chain_mma<4,8>(acc, ah, al, aB, aBL, laneB_off);
#pragma unroll
    for (int nt = 0; nt < 16; nt++) {
        int col = nt*8 + cl;
        float c0 = __ldg(&db1[col]), c1 = __ldg(&db1[col+1]);
        acc[nt][0] = fmaxf(acc[nt][0] + c0, 0.f);
        acc[nt][1] = fmaxf(acc[nt][1] + c1, 0.f);
        acc[nt][2] = fmaxf(acc[nt][2] + c0, 0.f);
        acc[nt][3] = fmaxf(acc[nt][3] + c1, 0.f);
    }
    chain_conv<8>(acc, ah, al);

    // ===== stage 4: h4 = relu(h3 @ dw2 + db2) -> H4s =====
    __syncthreads();
    chain_fillB(cs, g_cwh + 32768, g_cwl + 32768, 128, 128, tid);
    __syncthreads();
#pragma unroll
    for (int nt = 0; nt < 16; nt++)
#pragma unroll
        for (int q = 0; q < 4; q++) acc[nt][q] = 0.f;
    chain_mma<8,8>(acc, ah, al, aB, aBL, laneB_off);
    __syncthreads();
#pragma unroll
    for (int nt = 0; nt < 16; nt++) {
        int col = nt*8 + cl;
        float c0 = __ldg(&db2[col]), c1 = __ldg(&db2[col+1]);
        H4s[mr*H4_P + col]         = fmaxf(acc[nt][0] + c0, 0.f);
        H4s[mr*H4_P + col + 1]     = fmaxf(acc[nt][1] + c1, 0.f);
        H4s[(mr+8)*H4_P + col]     = fmaxf(acc[nt][2] + c0, 0.f);
        H4s[(mr+8)*H4_P + col + 1] = fmaxf(acc[nt][3] + c1, 0.f);
    }
    for (int i = tid; i < HID2_*TOUT_; i += 256) w3s[i] = dw3[i];
    for (int i = tid; i < H_*TOUT_;    i += 256) pjs[i] = dpj[i];
    __syncthreads();

    // ===== final: out = transpose(BN(h4 @ dw3 + db3 + e @ dpj)) =====
    {
        const int row = tid >> 1;
        const int ob  = (tid & 1) * 6;
        float facc[6];
#pragma unroll
        for (int o = 0; o < 6; o++) facc[o] = db3[ob + o];

        const float4* hr = (const float4*)&H4s[row * H4_P];
#pragma unroll 4
        for (int k4 = 0; k4 < HID2_/4; k4++) {
            float4 hv = hr[k4];
            float h[4] = {hv.x, hv.y, hv.z, hv.w};
#pragma unroll
            for (int q = 0; q < 4; q++) {
                int k = k4*4 + q;
#pragma unroll
                for (int o = 0; o < 6; o++)
                    facc[o] = fmaf(h[q], w3s[k*TOUT_ + ob + o], facc[o]);
            }
        }
        const float4* er = (const float4*)&Es[row * ES_P];
#pragma unroll 4
        for (int k4 = 0; k4 < H_/4; k4++) {
            float4 ev = er[k4];
            float e4[4] = {ev.x, ev.y, ev.z, ev.w};
#pragma unroll
            for (int q = 0; q < 4; q++) {
                int k = k4*4 + q;
#pragma unroll
                for (int o = 0; o < 6; o++)
                    facc[o] = fmaf(e4[q], pjs[k*TOUT_ + ob + o], facc[o]);
            }
        }

        const int gm = m0 + row;
        const int b = gm / N_, n = gm % N_;
#pragma unroll
        for (int o = 0; o < 6; o++) {
            int oo = ob + o;
            float c = (facc[o] - dbnm[oo]) * rsqrtf(dbnv[oo] + BN_EPS_) * dbng[oo] + dbnb[oo];
            out[((size_t)(b*TOUT_ + oo))*N_ + n] = c;
        }
    }
}

// ---------------- host launch ----------------
extern "C" void kernel_launch(void* const* d_in, const int* in_sizes, int n_in,
                              void* d_out, int out_size)
{
    const float* x        = (const float*)d_in[0];
    const float* W1       = (const float*)d_in[1];
    const float* W2       = (const float*)d_in[2];
    const float* enc_w1   = (const float*)d_in[3];
    const float* enc_b1   = (const float*)d_in[4];
    const float* enc_w2   = (const float*)d_in[5];
    const float* enc_b2   = (const float*)d_in[6];
    const float* enc_w3   = (const float*)d_in[7];
    const float* enc_b3   = (const float*)d_in[8];
    const float* enc_proj = (const float*)d_in[9];
    const float* enc_bn_g = (const float*)d_in[10];
    const float* enc_bn_b = (const float*)d_in[11];
    const float* enc_bn_m = (const float*)d_in[12];
    const float* enc_bn_v = (const float*)d_in[13];
    const float* dec_w1   = (const float*)d_in[14];
    const float* dec_b1   = (const float*)d_in[15];
    const float* dec_w2   = (const float*)d_in[16];
    const float* dec_b2   = (const float*)d_in[17];
    const float* dec_w3   = (const float*)d_in[18];
    const float* dec_b3   = (const float*)d_in[19];
    const float* dec_proj = (const float*)d_in[20];
    const float* dec_bn_g = (const float*)d_in[21];
    const float* dec_bn_b = (const float*)d_in[22];
    const float* dec_bn_m = (const float*)d_in[23];
    const float* dec_bn_v = (const float*)d_in[24];
    float* out = (float*)d_out;

    static int attr_done = 0;
    if (!attr_done) {
        cudaFuncSetAttribute(k_graph_mma, cudaFuncAttributeMaxDynamicSharedMemorySize, SG_BYTES);
        cudaFuncSetAttribute(k_pair_mma,  cudaFuncAttributeMaxDynamicSharedMemorySize, PIPE3_B);
        cudaFuncSetAttribute(k_chain,     cudaFuncAttributeMaxDynamicSharedMemorySize, CHAIN_BYTES);
        attr_done = 1;
    }

    // 5 launches total
    k_softprep  <<<((HID2_+H_)*TH_ + 49152 + 255)/256, 256>>>(
        x, enc_w1, enc_proj, enc_w2, enc_w3, dec_w1, dec_w2);            // 1
    k_graph_mma <<<dim3(N_/128, N_/128, B_), 256, SG_BYTES>>>(x);        // 2
    k_buildz    <<<(M_*TH_/8)/256, 256>>>(x, W1, W2);                    // 3 (gfin fused)
    k_pair_mma  <<<dim3(M_/128, 3), 256, PIPE3_B>>>(enc_b1);             // 4
    k_chain     <<<M_/128, 256, CHAIN_BYTES>>>(enc_b2, enc_b3,
        enc_bn_g, enc_bn_b, enc_bn_m, enc_bn_v, dec_b1, dec_b2,
        dec_w3, dec_b3, dec_proj,
        dec_bn_g, dec_bn_b, dec_bn_m, dec_bn_v, out);                    // 5
}

// round 17
// speedup vs baseline: 1.0190x; 1.0190x over previous
#include <cuda_runtime.h>
#include <cuda_bf16.h>
#include <math.h>
#include <stdint.h>

#define B_    8
#define T_    12
#define N_    1536
#define H_    64
#define TH_   768
#define HID2_ 128
#define TOUT_ 12
#define M_    (B_*N_)          // 12288
#define DELTA_   0.5f
#define ALPHA_   0.3f
#define KHOPS_   3.0f
#define KL_EPS_  1e-10f
#define BN_EPS_  1e-5f
#define DEG_MIN_ 1e-6f

typedef unsigned long long u64;

// ---------------- warp mma.sync bf16 + helpers ----------------
__device__ __forceinline__ void mma_bf16(float* c,
    uint32_t a0, uint32_t a1, uint32_t a2, uint32_t a3,
    uint32_t b0, uint32_t b1)
{
    asm volatile(
        "mma.sync.aligned.m16n8k16.row.col.f32.bf16.bf16.f32 "
        "{%0,%1,%2,%3}, {%4,%5,%6,%7}, {%8,%9}, {%0,%1,%2,%3};"
        : "+f"(c[0]), "+f"(c[1]), "+f"(c[2]), "+f"(c[3])
        : "r"(a0), "r"(a1), "r"(a2), "r"(a3), "r"(b0), "r"(b1));
}
__device__ __forceinline__ void ldsm_x4(uint32_t& r0, uint32_t& r1,
                                        uint32_t& r2, uint32_t& r3, uint32_t addr)
{
    asm volatile("ldmatrix.sync.aligned.m8n8.x4.shared.b16 {%0,%1,%2,%3}, [%4];"
        : "=r"(r0), "=r"(r1), "=r"(r2), "=r"(r3) : "r"(addr));
}
__device__ __forceinline__ uint32_t s2u(const void* p) {
    uint32_t a;
    asm("{ .reg .u64 t; cvta.to.shared.u64 t, %1; cvt.u32.u64 %0, t; }" : "=r"(a) : "l"(p));
    return a;
}
__device__ __forceinline__ void split_bf16(float v, __nv_bfloat16& h, __nv_bfloat16& l) {
    h = __float2bfloat16(v);
    l = __float2bfloat16(v - __bfloat162float(h));
}
__device__ __forceinline__ uint32_t mpack(bool m0, bool m1) {
    return (m0 ? 0x3F80u : 0u) | (m1 ? 0x3F800000u : 0u);
}
__device__ __forceinline__ void cp_async8(uint32_t saddr, const void* gaddr) {
    asm volatile("cp.async.ca.shared.global [%0], [%1], 8;" :: "r"(saddr), "l"(gaddr));
}
// split a pair to packed hi and lo bf16x2
__device__ __forceinline__ void hil(float a, float b, uint32_t& ph, uint32_t& pl) {
    __nv_bfloat16 ha = __float2bfloat16(a), hb = __float2bfloat16(b);
    __nv_bfloat16 la = __float2bfloat16(a - __bfloat162float(ha));
    __nv_bfloat16 lb = __float2bfloat16(b - __bfloat162float(hb));
    __nv_bfloat162 vh{ha, hb}, vl{la, lb};
    ph = *(uint32_t*)&vh;
    pl = *(uint32_t*)&vl;
}

#define KPCH 40
#define KP   24
#define XP   136

// k_pair_mma pipeline buffers (2-stage)
#define BUF_U16  15360
#define BUF_B    (BUF_U16*2)
#define PIPE2_B  (2*BUF_B)          // 61440 B -> 3 CTAs/SM

// bf16x3 ldmatrix inner step over one 32-k smem tile (A 128 rows, B 64 rows)
__device__ __forceinline__ void mma_tile(float acc[8][4],
    uint32_t aAh, uint32_t aAl, uint32_t aBh, uint32_t aBl,
    int laneA_off, int laneB_off)
{
#pragma unroll
    for (int ks = 0; ks < 2; ks++) {
        uint32_t ah[4], al[4];
        ldsm_x4(ah[0],ah[1],ah[2],ah[3], aAh + laneA_off + ks*32);
        ldsm_x4(al[0],al[1],al[2],al[3], aAl + laneA_off + ks*32);
#pragma unroll
        for (int t2 = 0; t2 < 4; t2++) {
            uint32_t bh[4], bl[4];
            ldsm_x4(bh[0],bh[1],bh[2],bh[3], aBh + laneB_off + t2*(16*KPCH*2) + ks*32);
            ldsm_x4(bl[0],bl[1],bl[2],bl[3], aBl + laneB_off + t2*(16*KPCH*2) + ks*32);
            mma_bf16(acc[2*t2],   ah[0],ah[1],ah[2],ah[3], bh[0],bh[1]);
            mma_bf16(acc[2*t2],   ah[0],ah[1],ah[2],ah[3], bl[0],bl[1]);
            mma_bf16(acc[2*t2],   al[0],al[1],al[2],al[3], bh[0],bh[1]);
            mma_bf16(acc[2*t2+1], ah[0],ah[1],ah[2],ah[3], bh[2],bh[3]);
            mma_bf16(acc[2*t2+1], ah[0],ah[1],ah[2],ah[3], bl[2],bl[3]);
            mma_bf16(acc[2*t2+1], al[0],al[1],al[2],al[3], bh[2],bh[3]);
        }
    }
}

__device__ __forceinline__ void cp_fill(uint32_t sbase,
    const __nv_bfloat16* __restrict__ gh, const __nv_bfloat16* __restrict__ gl,
    const __nv_bfloat16* __restrict__ wh, const __nv_bfloat16* __restrict__ wl,
    int m0, int n0, int KD, int k0, int tid)
{
#pragma unroll
    for (int q = 0; q < 4; q++) {
        int idx = q*256 + tid;
        int r = idx >> 3, c = (idx & 7) * 4;
        cp_async8(sbase + (r*KPCH + c)*2,          gh + (size_t)(m0+r)*KD + k0 + c);
        cp_async8(sbase + (5120 + r*KPCH + c)*2,   gl + (size_t)(m0+r)*KD + k0 + c);
    }
#pragma unroll
    for (int q = 0; q < 2; q++) {
        int idx = q*256 + tid;
        int r = idx >> 3, c = (idx & 7) * 4;
        cp_async8(sbase + (10240 + r*KPCH + c)*2,  wh + (size_t)(n0+r)*KD + k0 + c);
        cp_async8(sbase + (12800 + r*KPCH + c)*2,  wl + (size_t)(n0+r)*KD + k0 + c);
    }
    asm volatile("cp.async.commit_group;" ::: "memory");
}

// 2-stage pipeline, ONE sync per iteration.
// Order per iter: wait(fill of buf[it&1], issued at it-1) -> sync (also orders
// mma(it-1) on the other buffer) -> issue fill(buf[(it+1)&1]) (safe: that buffer's
// mma finished at it-1, ordered by this sync) -> mma(buf[it&1]) overlapping the fill.
__device__ __forceinline__ void pipe_loop2(float acc[8][4], uint32_t dbase,
    const __nv_bfloat16* __restrict__ Ahp, const __nv_bfloat16* __restrict__ Alp,
    const __nv_bfloat16* __restrict__ Bhp, const __nv_bfloat16* __restrict__ Blp,
    int m0, int n0, int KD, int NITER, int tid, int laneA_off, int laneB_off)
{
    cp_fill(dbase, Ahp, Alp, Bhp, Blp, m0, n0, KD, 0, tid);
    for (int it = 0; it < NITER; it++) {
        asm volatile("cp.async.wait_group 0;" ::: "memory");
        __syncthreads();
        uint32_t sb = dbase + (it & 1) * BUF_B;
        if (it + 1 < NITER)
            cp_fill(dbase + ((it+1) & 1) * BUF_B, Ahp, Alp, Bhp, Blp,
                    m0, n0, KD, (it+1)*32, tid);
        mma_tile(acc, sb, sb + 5120*2, sb + 10240*2, sb + 12800*2, laneA_off, laneB_off);
    }
}

// ---------------- device scratch ----------------
__device__ float g_s  [M_];
__device__ float g_deg[M_];
__device__ float g_ind[M_];
__device__ __align__(16) float g_af[M_*T_];
__device__ __align__(16) float g_ab[M_*T_];
__device__ __align__(16) __nv_bfloat16 g_pbh[(size_t)M_*16];
__device__ __align__(16) __nv_bfloat16 g_pbl[(size_t)M_*16];
__device__ __align__(16) __nv_bfloat16 g_lbh[(size_t)M_*16];
__device__ __align__(16) __nv_bfloat16 g_lbl[(size_t)M_*16];
__device__ __align__(16) __nv_bfloat16 g_zh[(size_t)M_*TH_];
__device__ __align__(16) __nv_bfloat16 g_zl[(size_t)M_*TH_];
__device__ __align__(16) __nv_bfloat16 g_wh[(size_t)(HID2_+H_)*TH_];
__device__ __align__(16) __nv_bfloat16 g_wl[(size_t)(HID2_+H_)*TH_];
__device__ __align__(16) __nv_bfloat16 g_cwh[49152];
__device__ __align__(16) __nv_bfloat16 g_cwl[49152];
__device__ __align__(16) __nv_bfloat16 g_h1h[(size_t)M_*HID2_];
__device__ __align__(16) __nv_bfloat16 g_h1l[(size_t)M_*HID2_];
__device__ __align__(16) float g_zp[(size_t)M_*H_];

// ---------------- K1: fused softmax + weight prep ----------------
__global__ void __launch_bounds__(256) k_softprep(
    const float* __restrict__ x,
    const float* __restrict__ w1, const float* __restrict__ proj,
    const float* __restrict__ w2, const float* __restrict__ w3,
    const float* __restrict__ dw1, const float* __restrict__ dw2)
{
    int idx = blockIdx.x * 256 + threadIdx.x;

    if (idx < M_) {
        int bn = idx;
        int b = bn / N_, n = bn % N_;
        float v[T_];
        float mx = -1e30f;
#pragma unroll
        for (int t = 0; t < T_; t++) {
            v[t] = x[((size_t)(b*T_ + t))*N_ + n];
            mx = fmaxf(mx, v[t]);
        }
        float sum = 0.f;
#pragma unroll
        for (int t = 0; t < T_; t++) { v[t] = expf(v[t] - mx); sum += v[t]; }
        float inv = 1.f / sum;
        float s = 0.f;
        size_t b16 = (size_t)bn * 16;
        size_t b12 = (size_t)bn * T_;
#pragma unroll
        for (int t = 0; t < T_; t++) {
            float p  = v[t] * inv;
            float lp = logf(p + KL_EPS_);
            __nv_bfloat16 ph, pl, lh, ll;
            split_bf16(p,  ph, pl);
            split_bf16(lp, lh, ll);
            g_pbh[b16 + t] = ph;  g_pbl[b16 + t] = pl;
            g_lbh[b16 + t] = lh;  g_lbl[b16 + t] = ll;
            g_af[b12 + t] = 0.f;
            g_ab[b12 + t] = 0.f;
            s = fmaf(p, lp, s);
        }
#pragma unroll
        for (int t = T_; t < 16; t++) {
            g_pbh[b16 + t] = __float2bfloat16(0.f);
            g_pbl[b16 + t] = __float2bfloat16(0.f);
            g_lbh[b16 + t] = __float2bfloat16(0.f);
            g_lbl[b16 + t] = __float2bfloat16(0.f);
        }
        g_s[bn] = s;
        g_deg[bn] = 0.f;
        g_ind[bn] = 0.f;
    }

    if (idx < (HID2_+H_)*TH_) {
        int n = idx / TH_, k = idx % TH_;
        float v = (n < HID2_) ? w1[(size_t)k*HID2_ + n] : proj[(size_t)k*H_ + (n - HID2_)];
        __nv_bfloat16 h, l;
        split_bf16(v, h, l);
        g_wh[idx] = h;
        g_wl[idx] = l;
        return;
    }
    int c = idx - (HID2_+H_)*TH_;
    if (c >= 49152) return;
    float v;
    if (c < 16384)      { int j = c;         int n = j/128, k = j%128; v = w2 [(size_t)k*HID2_ + n]; }
    else if (c < 24576) { int j = c - 16384; int n = j/128, k = j%128; v = w3 [(size_t)k*H_    + n]; }
    else if (c < 32768) { int j = c - 24576; int n = j/64,  k = j%64;  v = dw1[(size_t)k*HID2_ + n]; }
    else                { int j = c - 32768; int n = j/128, k = j%128; v = dw2[(size_t)k*HID2_ + n]; }
    __nv_bfloat16 h, l;
    split_bf16(v, h, l);
    g_cwh[c] = h;
    g_cwl[c] = l;
}

// ---------------- K2: graph via tensor cores (frozen) ----------------
#define SG_PIH 0
#define SG_PIL 3072
#define SG_PJH 6144
#define SG_PJL 9216
#define SG_LIH 12288
#define SG_LIL 15360
#define SG_LJH 18432
#define SG_LJL 21504
#define SG_XH  24576
#define SG_XL  (24576+2176)
#define SG_M   (24576+4352)
#define SG_TOT (SG_M + 128*XP)
#define SG_BYTES (SG_TOT*2)

__global__ void __launch_bounds__(256) k_graph_mma(const float* __restrict__ x) {
    extern __shared__ __align__(16) __nv_bfloat16 sm[];
    __shared__ float ssi[128], ssj[128];

    const int tid  = threadIdx.x;
    const int w    = tid >> 5, lane = tid & 31;
    const int b    = blockIdx.z;
    const int i0   = blockIdx.x * 128;
    const int j0   = blockIdx.y * 128;
    const int bN   = b * N_;

#pragma unroll
    for (int q = 0; q < 4; q++) {
        int idx = q*256 + tid;
        int a = idx >> 7, r = idx & 127;
        const __nv_bfloat16* src;
        __nv_bfloat16* dst;
        switch (a) {
            case 0: src = g_pbh + (size_t)(bN+i0+r)*16; dst = sm + SG_PIH + r*KP; break;
            case 1: src = g_pbl + (size_t)(bN+i0+r)*16; dst = sm + SG_PIL + r*KP; break;
            case 2: src = g_pbh + (size_t)(bN+j0+r)*16; dst = sm + SG_PJH + r*KP; break;
            case 3: src = g_pbl + (size_t)(bN+j0+r)*16; dst = sm + SG_PJL + r*KP; break;
            case 4: src = g_lbh + (size_t)(bN+i0+r)*16; dst = sm + SG_LIH + r*KP; break;
            case 5: src = g_lbl + (size_t)(bN+i0+r)*16; dst = sm + SG_LIL + r*KP; break;
            case 6: src = g_lbh + (size_t)(bN+j0+r)*16; dst = sm + SG_LJH + r*KP; break;
            default:src = g_lbl + (size_t)(bN+j0+r)*16; dst = sm + SG_LJL + r*KP; break;
        }
        *(uint4*)dst       = *(const uint4*)src;
        *(uint4*)(dst + 8) = *(const uint4*)(src + 8);
    }
#pragma unroll
    for (int q = 0; q < 8; q++) {
        int idx = q*256 + tid;
        int t = idx >> 7, j = idx & 127;
        float v = (t < T_) ? x[((size_t)(b*T_ + t))*N_ + j0 + j] : (t == 12 ? 1.f : 0.f);
        __nv_bfloat16 h, l;
        split_bf16(v, h, l);
        sm[SG_XH + t*XP + j] = h;
        sm[SG_XL + t*XP + j] = l;
    }
    if (tid < 128) ssi[tid] = g_s[bN + i0 + tid];
    else           ssj[tid-128] = g_s[bN + j0 + tid - 128];
    __syncthreads();

    const int r0   = w*16 + (lane >> 2);
    const int koff = (lane & 3) * 2;
    __nv_bfloat16* Mm = sm + SG_M;
    const __nv_bfloat16* Xh = sm + SG_XH;
    const __nv_bfloat16* Xl = sm + SG_XL;

    float acc[16][4];

    // ===== Phase A =====
    {
#pragma unroll
        for (int nt = 0; nt < 16; nt++)
#pragma unroll
            for (int q = 0; q < 4; q++) acc[nt][q] = 0.f;
        uint32_t ah0 = *(const uint32_t*)&sm[SG_PIH + r0*KP + koff];
        uint32_t ah1 = *(const uint32_t*)&sm[SG_PIH + (r0+8)*KP + koff];
        uint32_t ah2 = *(const uint32_t*)&sm[SG_PIH + r0*KP + koff + 8];
        uint32_t ah3 = *(const uint32_t*)&sm[SG_PIH + (r0+8)*KP + koff + 8];
        uint32_t al0 = *(const uint32_t*)&sm[SG_PIL + r0*KP + koff];
        uint32_t al1 = *(const uint32_t*)&sm[SG_PIL + (r0+8)*KP + koff];
        uint32_t al2 = *(const uint32_t*)&sm[SG_PIL + r0*KP + koff + 8];
        uint32_t al3 = *(const uint32_t*)&sm[SG_PIL + (r0+8)*KP + koff + 8];
#pragma unroll
        for (int nt = 0; nt < 16; nt++) {
            int br = nt*8 + (lane >> 2);
            uint32_t bh0 = *(const uint32_t*)&sm[SG_LJH + br*KP + koff];
            uint32_t bh1 = *(const uint32_t*)&sm[SG_LJH + br*KP + koff + 8];
            uint32_t bl0 = *(const uint32_t*)&sm[SG_LJL + br*KP + koff];
            uint32_t bl1 = *(const uint32_t*)&sm[SG_LJL + br*KP + koff + 8];
            mma_bf16(acc[nt], ah0,ah1,ah2,ah3, bh0,bh1);
            mma_bf16(acc[nt], ah0,ah1,ah2,ah3, bl0,bl1);
            mma_bf16(acc[nt], al0,al1,al2,al3, bh0,bh1);
        }
        float si0 = ssi[r0], si1 = ssi[r0+8];
#pragma unroll
        for (int nt = 0; nt < 16; nt++) {
            *(uint32_t*)&Mm[r0*XP + nt*8 + koff] =
                mpack((si0 - acc[nt][0]) < DELTA_, (si0 - acc[nt][1]) < DELTA_);
            *(uint32_t*)&Mm[(r0+8)*XP + nt*8 + koff] =
                mpack((si1 - acc[nt][2]) < DELTA_, (si1 - acc[nt][3]) < DELTA_);
        }
        __syncwarp();
        float acc2[2][4];
#pragma unroll
        for (int nt = 0; nt < 2; nt++)
#pragma unroll
            for (int q = 0; q < 4; q++) acc2[nt][q] = 0.f;
#pragma unroll
        for (int kk = 0; kk < 8; kk++) {
            uint32_t a0 = *(const uint32_t*)&Mm[r0*XP + kk*16 + koff];
            uint32_t a1 = *(const uint32_t*)&Mm[(r0+8)*XP + kk*16 + koff];
            uint32_t a2 = *(const uint32_t*)&Mm[r0*XP + kk*16 + koff + 8];
            uint32_t a3 = *(const uint32_t*)&Mm[(r0+8)*XP + kk*16 + koff + 8];
#pragma unroll
            for (int nt = 0; nt < 2; nt++) {
                int br = nt*8 + (lane >> 2);
                uint32_t xh0 = *(const uint32_t*)&Xh[br*XP + kk*16 + koff];
                uint32_t xh1 = *(const uint32_t*)&Xh[br*XP + kk*16 + koff + 8];
                uint32_t xl0 = *(const uint32_t*)&Xl[br*XP + kk*16 + koff];
                uint32_t xl1 = *(const uint32_t*)&Xl[br*XP + kk*16 + koff + 8];
                mma_bf16(acc2[nt], a0,a1,a2,a3, xh0,xh1);
                mma_bf16(acc2[nt], a0,a1,a2,a3, xl0,xl1);
            }
        }
        int gi0 = bN + i0 + r0;
#pragma unroll
        for (int nt = 0; nt < 2; nt++) {
            int c0 = nt*8 + koff;
#pragma unroll
            for (int q = 0; q < 4; q++) {
                int cc = c0 + (q & 1);
                int gi = gi0 + (q >> 1) * 8;
                if (cc < T_)       atomicAdd(&g_af[(size_t)gi*T_ + cc], acc2[nt][q]);
                else if (cc == 12) atomicAdd(&g_deg[gi], acc2[nt][q]);
            }
        }
    }

    // ===== Phase B =====
    {
#pragma unroll
        for (int nt = 0; nt < 16; nt++)
#pragma unroll
            for (int q = 0; q < 4; q++) acc[nt][q] = 0.f;
        uint32_t ah0 = *(const uint32_t*)&sm[SG_PJH + r0*KP + koff];
        uint32_t ah1 = *(const uint32_t*)&sm[SG_PJH + (r0+8)*KP + koff];
        uint32_t ah2 = *(const uint32_t*)&sm[SG_PJH + r0*KP + koff + 8];
        uint32_t ah3 = *(const uint32_t*)&sm[SG_PJH + (r0+8)*KP + koff + 8];
        uint32_t al0 = *(const uint32_t*)&sm[SG_PJL + r0*KP + koff];
        uint32_t al1 = *(const uint32_t*)&sm[SG_PJL + (r0+8)*KP + koff];
        uint32_t al2 = *(const uint32_t*)&sm[SG_PJL + r0*KP + koff + 8];
        uint32_t al3 = *(const uint32_t*)&sm[SG_PJL + (r0+8)*KP + koff + 8];
#pragma unroll
        for (int nt = 0; nt < 16; nt++) {
            int br = nt*8 + (lane >> 2);
            uint32_t bh0 = *(const uint32_t*)&sm[SG_LIH + br*KP + koff];
            uint32_t bh1 = *(const uint32_t*)&sm[SG_LIH + br*KP + koff + 8];
            uint32_t bl0 = *(const uint32_t*)&sm[SG_LIL + br*KP + koff];
            uint32_t bl1 = *(const uint32_t*)&sm[SG_LIL + br*KP + koff + 8];
            mma_bf16(acc[nt], ah0,ah1,ah2,ah3, bh0,bh1);
            mma_bf16(acc[nt], ah0,ah1,ah2,ah3, bl0,bl1);
            mma_bf16(acc[nt], al0,al1,al2,al3, bh0,bh1);
        }
        __syncthreads();
        float sj0 = ssj[r0], sj1 = ssj[r0+8];
        const __nv_bfloat16 one = __float2bfloat16(1.f);
        const __nv_bfloat16 zro = __float2bfloat16(0.f);
#pragma unroll
        for (int nt = 0; nt < 16; nt++) {
            int ci = nt*8 + koff;
            Mm[(ci    )*XP + r0    ] = ((sj0 - acc[nt][0]) < DELTA_) ? one : zro;
            Mm[(ci + 1)*XP + r0    ] = ((sj0 - acc[nt][1]) < DELTA_) ? one : zro;
            Mm[(ci    )*XP + r0 + 8] = ((sj1 - acc[nt][2]) < DELTA_) ? one : zro;
            Mm[(ci + 1)*XP + r0 + 8] = ((sj1 - acc[nt][3]) < DELTA_) ? one : zro;
        }
        __syncthreads();
        float acc2[2][4];
#pragma unroll
        for (int nt = 0; nt < 2; nt++)
#pragma unroll
            for (int q = 0; q < 4; q++) acc2[nt][q] = 0.f;
#pragma unroll
        for (int kk = 0; kk < 8; kk++) {
            uint32_t a0 = *(const uint32_t*)&Mm[r0*XP + kk*16 + koff];
            uint32_t a1 = *(const uint32_t*)&Mm[(r0+8)*XP + kk*16 + koff];
            uint32_t a2 = *(const uint32_t*)&Mm[r0*XP + kk*16 + koff + 8];
            uint32_t a3 = *(const uint32_t*)&Mm[(r0+8)*XP + kk*16 + koff + 8];
#pragma unroll
            for (int nt = 0; nt < 2; nt++) {
                int br = nt*8 + (lane >> 2);
                uint32_t xh0 = *(const uint32_t*)&Xh[br*XP + kk*16 + koff];
                uint32_t xh1 = *(const uint32_t*)&Xh[br*XP + kk*16 + koff + 8];
                uint32_t xl0 = *(const uint32_t*)&Xl[br*XP + kk*16 + koff];
                uint32_t xl1 = *(const uint32_t*)&Xl[br*XP + kk*16 + koff + 8];
                mma_bf16(acc2[nt], a0,a1,a2,a3, xh0,xh1);
                mma_bf16(acc2[nt], a0,a1,a2,a3, xl0,xl1);
            }
        }
        int gi0 = bN + i0 + r0;
#pragma unroll
        for (int nt = 0; nt < 2; nt++) {
            int c0 = nt*8 + koff;
#pragma unroll
            for (int q = 0; q < 4; q++) {
                int cc = c0 + (q & 1);
                int gi = gi0 + (q >> 1) * 8;
                if (cc < T_)       atomicAdd(&g_ab[(size_t)gi*T_ + cc], acc2[nt][q]);
                else if (cc == 12) atomicAdd(&g_ind[gi], acc2[nt][q]);
            }
        }
    }
}

// ---------------- K3: build z (gfin fused) ----------------
__global__ void __launch_bounds__(256) k_buildz(const float* __restrict__ x,
                                                const float* __restrict__ W1,
                                                const float* __restrict__ W2) {
    int idx8 = blockIdx.x * 256 + threadIdx.x;
    if (idx8 >= M_*TH_/8) return;
    int row = idx8 / (TH_/8);
    int c8  = idx8 % (TH_/8);
    int t   = c8 >> 3;
    int h8  = (c8 & 7) * 8;
    int b = row / N_, n = row % N_;
    float xv = x[((size_t)(b*T_ + t))*N_ + n];
    float rf = (KHOPS_ * ALPHA_)        * __frcp_rn(fmaxf(__ldg(&g_deg[row]), DEG_MIN_));
    float rb = (KHOPS_ * (1.f-ALPHA_))  * __frcp_rn(fmaxf(__ldg(&g_ind[row]), DEG_MIN_));
    float gg = rf * __ldg(&g_af[(size_t)row*T_ + t]) + rb * __ldg(&g_ab[(size_t)row*T_ + t]);
    float4 w1a = *(const float4*)&W1[h8];
    float4 w1b = *(const float4*)&W1[h8 + 4];
    float4 w2a = *(const float4*)&W2[h8];
    float4 w2b = *(const float4*)&W2[h8 + 4];
    float v[8];
    v[0] = fmaxf(fmaf(xv, w1a.x, gg * w2a.x), 0.f);
    v[1] = fmaxf(fmaf(xv, w1a.y, gg * w2a.y), 0.f);
    v[2] = fmaxf(fmaf(xv, w1a.z, gg * w2a.z), 0.f);
    v[3] = fmaxf(fmaf(xv, w1a.w, gg * w2a.w), 0.f);
    v[4] = fmaxf(fmaf(xv, w1b.x, gg * w2b.x), 0.f);
    v[5] = fmaxf(fmaf(xv, w1b.y, gg * w2b.y), 0.f);
    v[6] = fmaxf(fmaf(xv, w1b.z, gg * w2b.z), 0.f);
    v[7] = fmaxf(fmaf(xv, w1b.w, gg * w2b.w), 0.f);
    uint4 oh, ol;
#pragma unroll
    for (int q = 0; q < 8; q += 2) {
        uint32_t ph, pl;
        hil(v[q], v[q+1], ph, pl);
        ((uint32_t*)&oh)[q>>1] = ph;
        ((uint32_t*)&ol)[q>>1] = pl;
    }
    size_t o = (size_t)idx8 * 8;
    *(uint4*)&g_zh[o] = oh;
    *(uint4*)&g_zl[o] = ol;
}

// ---------------- K4: 2-stage pipelined bf16x3 fused GEMM (3 CTAs/SM) ----------------
__global__ void __launch_bounds__(256, 3) k_pair_mma(const float* __restrict__ b1v) {
    extern __shared__ __align__(16) __nv_bfloat16 dsm[];
    const int tid  = threadIdx.x;
    const int w    = tid >> 5, lane = tid & 31;
    const int m0   = blockIdx.x * 128;
    const int n0   = blockIdx.y * 64;

    float acc[8][4];
#pragma unroll
    for (int t = 0; t < 8; t++)
#pragma unroll
        for (int j = 0; j < 4; j++) acc[t][j] = 0.f;

    const uint32_t dbase = s2u(dsm);
    const int laneA_off = ((w*16 + (lane & 15))*KPCH)*2 + ((lane>>4)&1)*16;
    const int laneB_off = (((lane & 7) + ((lane>>4)&1)*8)*KPCH)*2 + ((lane>>3)&1)*16;

    pipe_loop2(acc, dbase, g_zh, g_zl, g_wh, g_wl, m0, n0, TH_, TH_/32, tid,
               laneA_off, laneB_off);

    const int m  = m0 + w*16 + (lane >> 2);
    const int cl = (lane & 3) * 2;
    if (n0 < HID2_) {
#pragma unroll
        for (int t = 0; t < 8; t++) {
            int col = n0 + t*8 + cl;
            float b0 = __ldg(&b1v[col]), b1 = __ldg(&b1v[col+1]);
            float v00 = fmaxf(acc[t][0] + b0, 0.f), v01 = fmaxf(acc[t][1] + b1, 0.f);
            float v10 = fmaxf(acc[t][2] + b0, 0.f), v11 = fmaxf(acc[t][3] + b1, 0.f);
            uint32_t ph0, pl0, ph1, pl1;
            hil(v00, v01, ph0, pl0);
            hil(v10, v11, ph1, pl1);
            *(uint32_t*)&g_h1h[(size_t)m*HID2_ + col]     = ph0;
            *(uint32_t*)&g_h1l[(size_t)m*HID2_ + col]     = pl0;
            *(uint32_t*)&g_h1h[(size_t)(m+8)*HID2_ + col] = ph1;
            *(uint32_t*)&g_h1l[(size_t)(m+8)*HID2_ + col] = pl1;
        }
    } else {
#pragma unroll
        for (int t = 0; t < 8; t++) {
            int col = t*8 + cl;
            *(float2*)&g_zp[(size_t)m*H_ + col]     = make_float2(acc[t][0], acc[t][1]);
            *(float2*)&g_zp[(size_t)(m+8)*H_ + col] = make_float2(acc[t][2], acc[t][3]);
        }
    }
}

// ---------------- K5: fused register-chained MLP tail + final stage ----------------
#define CCHA 5120
#define CSA_L 20480
#define CSB   40960
#define CSB_L 61440
#define CHAIN_BYTES (81920*2)
#define ES_OFF   0
#define ES_P     68
#define H4_OFF   34816
#define H4_P     132
#define W3S_OFF  102400
#define PJS_OFF  108544

__device__ __forceinline__ void chain_fillB(__nv_bfloat16* cs,
    const __nv_bfloat16* __restrict__ wh, const __nv_bfloat16* __restrict__ wl,
    int NR, int KD, int tid)
{
    for (int i = tid; i < NR*KD/4; i += 256) {
        int r  = i / (KD/4);
        int k4 = (i % (KD/4)) * 4;
        int off = (k4 >> 5)*CCHA + r*KPCH + (k4 & 31);
        *(uint2*)&cs[CSB   + off] = *(const uint2*)&wh[(size_t)r*KD + k4];
        *(uint2*)&cs[CSB_L + off] = *(const uint2*)&wl[(size_t)r*KD + k4];
    }
}

template<int NK16, int NNT2>
__device__ __forceinline__ void chain_mma(float (*acc)[4],
    const uint32_t (*ah)[4], const uint32_t (*al)[4],
    uint32_t aB, uint32_t aBL, int laneB_off)
{
#pragma unroll
    for (int kg = 0; kg < NK16; kg++) {
        uint32_t addr  = aB  + (kg>>1)*(CCHA*2) + laneB_off + (kg&1)*32;
        uint32_t addrl = aBL + (kg>>1)*(CCHA*2) + laneB_off + (kg&1)*32;
#pragma unroll
        for (int t2 = 0; t2 < NNT2; t2++) {
            uint32_t bh[4], bl[4];
            ldsm_x4(bh[0],bh[1],bh[2],bh[3], addr  + t2*(16*KPCH*2));
            ldsm_x4(bl[0],bl[1],bl[2],bl[3], addrl + t2*(16*KPCH*2));
            mma_bf16(acc[2*t2],   ah[kg][0],ah[kg][1],ah[kg][2],ah[kg][3], bh[0],bh[1]);
            mma_bf16(acc[2*t2],   ah[kg][0],ah[kg][1],ah[kg][2],ah[kg][3], bl[0],bl[1]);
            mma_bf16(acc[2*t2],   al[kg][0],al[kg][1],al[kg][2],al[kg][3], bh[0],bh[1]);
            mma_bf16(acc[2*t2+1], ah[kg][0],ah[kg][1],ah[kg][2],ah[kg][3], bh[2],bh[3]);
            mma_bf16(acc[2*t2+1], ah[kg][0],ah[kg][1],ah[kg][2],ah[kg][3], bl[2],bl[3]);
            mma_bf16(acc[2*t2+1], al[kg][0],al[kg][1],al[kg][2],al[kg][3], bh[2],bh[3]);
        }
    }
}

template<int NK16>
__device__ __forceinline__ void chain_conv(const float (*acc)[4],
    uint32_t (*ah)[4], uint32_t (*al)[4])
{
#pragma unroll
    for (int kg = 0; kg < NK16; kg++) {
        hil(acc[2*kg][0],   acc[2*kg][1],   ah[kg][0], al[kg][0]);
        hil(acc[2*kg][2],   acc[2*kg][3],   ah[kg][1], al[kg][1]);
        hil(acc[2*kg+1][0], acc[2*kg+1][1], ah[kg][2], al[kg][2]);
        hil(acc[2*kg+1][2], acc[2*kg+1][3], ah[kg][3], al[kg][3]);
    }
}

__global__ void __launch_bounds__(256) k_chain(
    const float* __restrict__ b2,  const float* __restrict__ b3,
    const float* __restrict__ bng, const float* __restrict__ bnb,
    const float* __restrict__ bnm, const float* __restrict__ bnv,
    const float* __restrict__ db1, const float* __restrict__ db2,
    const float* __restrict__ dw3, const float* __restrict__ db3,
    const float* __restrict__ dpj,
    const float* __restrict__ dbng, const float* __restrict__ dbnb,
    const float* __restrict__ dbnm, const float* __restrict__ dbnv,
    float* __restrict__ out)
{
    extern __shared__ __align__(16) __nv_bfloat16 cs[];
    const int tid  = threadIdx.x;
    const int w    = tid >> 5, lane = tid & 31;
    const int m0   = blockIdx.x * 128;
    const int mr   = w*16 + (lane >> 2);
    const int m    = m0 + mr;
    const int cl   = (lane & 3) * 2;
    const uint32_t csb = s2u(cs);
    const int laneA_off = ((w*16 + (lane & 15))*KPCH)*2 + ((lane>>4)&1)*16;
    const int laneB_off = (((lane & 7) + ((lane>>4)&1)*8)*KPCH)*2 + ((lane>>3)&1)*16;
    const uint32_t aB = csb + CSB*2, aBL = csb + CSB_L*2;
    float* Es  = (float*)((char*)cs + ES_OFF);
    float* H4s = (float*)((char*)cs + H4_OFF);
    float* w3s = (float*)((char*)cs + W3S_OFF);
    float* pjs = (float*)((char*)cs + PJS_OFF);

    uint32_t ah[8][4], al[8][4];
    float acc[16][4];

    for (int i = tid; i < 128*128/4; i += 256) {
        int r  = i >> 5;
        int k4 = (i & 31) * 4;
        int off = (k4 >> 5)*CCHA + r*KPCH + (k4 & 31);
        *(uint2*)&cs[off]         = *(const uint2*)&g_h1h[(size_t)(m0+r)*HID2_ + k4];
        *(uint2*)&cs[CSA_L + off] = *(const uint2*)&g_h1l[(size_t)(m0+r)*HID2_ + k4];
    }
    chain_fillB(cs, g_cwh, g_cwl, 128, 128, tid);
    __syncthreads();

#pragma unroll
    for (int kg = 0; kg < 8; kg++) {
        ldsm_x4(ah[kg][0],ah[kg][1],ah[kg][2],ah[kg][3],
                csb + (kg>>1)*(CCHA*2) + laneA_off + (kg&1)*32);
        ldsm_x4(al[kg][0],al[kg][1],al[kg][2],al[kg][3],
                csb + CSA_L*2 + (kg>>1)*(CCHA*2) + laneA_off + (kg&1)*32);
    }
    __syncthreads();

    // ===== stage 1: h2 = relu(h1 @ w2 + b2) =====
#pragma unroll
    for (int nt = 0; nt < 16; nt++)
#pragma unroll
        for (int q = 0; q < 4; q++) acc[nt][q] = 0.f;
    chain_mma<8,8>(acc, ah, al, aB, aBL, laneB_off);
#pragma unroll
    for (int nt = 0; nt < 16; nt++) {
        int col = nt*8 + cl;
        float c0 = __ldg(&b2[col]), c1 = __ldg(&b2[col+1]);
        acc[nt][0] = fmaxf(acc[nt][0] + c0, 0.f);
        acc[nt][1] = fmaxf(acc[nt][1] + c1, 0.f);
        acc[nt][2] = fmaxf(acc[nt][2] + c0, 0.f);
        acc[nt][3] = fmaxf(acc[nt][3] + c1, 0.f);
    }
    chain_conv<8>(acc, ah, al);

    // ===== stage 2: e = BN(h2 @ w3 + b3 + zp) -> Es =====
    __syncthreads();
    chain_fillB(cs, g_cwh + 16384, g_cwl + 16384, 64, 128, tid);
    __syncthreads();
#pragma unroll
    for (int nt = 0; nt < 8; nt++)
#pragma unroll
        for (int q = 0; q < 4; q++) acc[nt][q] = 0.f;
    chain_mma<8,4>(acc, ah, al, aB, aBL, laneB_off);
#pragma unroll
    for (int nt = 0; nt < 8; nt++) {
        int col = nt*8 + cl;
        float c0 = __ldg(&b3[col]), c1 = __ldg(&b3[col+1]);
        float v0 = acc[nt][0] + c0 + g_zp[(size_t)m*H_ + col];
        float v1 = acc[nt][1] + c1 + g_zp[(size_t)m*H_ + col + 1];
        float v2 = acc[nt][2] + c0 + g_zp[(size_t)(m+8)*H_ + col];
        float v3 = acc[nt][3] + c1 + g_zp[(size_t)(m+8)*H_ + col + 1];
        float s0 = rsqrtf(__ldg(&bnv[col])   + BN_EPS_) * __ldg(&bng[col]);
        float s1 = rsqrtf(__ldg(&bnv[col+1]) + BN_EPS_) * __ldg(&bng[col+1]);
        float m0v = __ldg(&bnm[col]), m1v = __ldg(&bnm[col+1]);
        float a0 = __ldg(&bnb[col]),  a1 = __ldg(&bnb[col+1]);
        v0 = (v0 - m0v) * s0 + a0;
        v1 = (v1 - m1v) * s1 + a1;
        v2 = (v2 - m0v) * s0 + a0;
        v3 = (v3 - m1v) * s1 + a1;
        Es[mr*ES_P + col]     = v0;
        Es[mr*ES_P + col + 1] = v1;
        Es[(mr+8)*ES_P + col]     = v2;
        Es[(mr+8)*ES_P + col + 1] = v3;
        acc[nt][0] = v0; acc[nt][1] = v1; acc[nt][2] = v2; acc[nt][3] = v3;
    }
    chain_conv<4>(acc, ah, al);

    // ===== stage 3: h3 = relu(e @ dw1 + db1) =====
    __syncthreads();
    chain_fillB(cs, g_cwh + 24576, g_cwl + 24576, 128, 64, tid);
    __syncthreads();
#pragma unroll
    for (int nt = 0; nt < 16; nt++)
#pragma unroll
        for (int q = 0; q < 4; q++) acc[nt][q] = 0.f;
    chain_mma<4,8>(acc, ah, al, aB, aBL, laneB_off);
#pragma unroll
    for (int nt = 0; nt < 16; nt++) {
        int col = nt*8 + cl;
        float c0 = __ldg(&db1[col]), c1 = __ldg(&db1[col+1]);
        acc[nt][0] = fmaxf(acc[nt][0] + c0, 0.f);
        acc[nt][1] = fmaxf(acc[nt][1] + c1, 0.f);
        acc[nt][2] = fmaxf(acc[nt][2] + c0, 0.f);
        acc[nt][3] = fmaxf(acc[nt][3] + c1, 0.f);
    }
    chain_conv<8>(acc, ah, al);

    // ===== stage 4: h4 = relu(h3 @ dw2 + db2) -> H4s =====
    __syncthreads();
    chain_fillB(cs, g_cwh + 32768, g_cwl + 32768, 128, 128, tid);
    __syncthreads();
#pragma unroll
    for (int nt = 0; nt < 16; nt++)
#pragma unroll
        for (int q = 0; q < 4; q++) acc[nt][q] = 0.f;
    chain_mma<8,8>(acc, ah, al, aB, aBL, laneB_off);
    __syncthreads();
#pragma unroll
    for (int nt = 0; nt < 16; nt++) {
        int col = nt*8 + cl;
        float c0 = __ldg(&db2[col]), c1 = __ldg(&db2[col+1]);
        H4s[mr*H4_P + col]         = fmaxf(acc[nt][0] + c0, 0.f);
        H4s[mr*H4_P + col + 1]     = fmaxf(acc[nt][1] + c1, 0.f);
        H4s[(mr+8)*H4_P + col]     = fmaxf(acc[nt][2] + c0, 0.f);
        H4s[(mr+8)*H4_P + col + 1] = fmaxf(acc[nt][3] + c1, 0.f);
    }
    for (int i = tid; i < HID2_*TOUT_; i += 256) w3s[i] = dw3[i];
    for (int i = tid; i < H_*TOUT_;    i += 256) pjs[i] = dpj[i];
    __syncthreads();

    // ===== final: out = transpose(BN(h4 @ dw3 + db3 + e @ dpj)) =====
    {
        const int row = tid >> 1;
        const int ob  = (tid & 1) * 6;
        float facc[6];
#pragma unroll
        for (int o = 0; o < 6; o++) facc[o] = db3[ob + o];

        const float4* hr = (const float4*)&H4s[row * H4_P];
#pragma unroll 4
        for (int k4 = 0; k4 < HID2_/4; k4++) {
            float4 hv = hr[k4];
            float h[4] = {hv.x, hv.y, hv.z, hv.w};
#pragma unroll
            for (int q = 0; q < 4; q++) {
                int k = k4*4 + q;
#pragma unroll
                for (int o = 0; o < 6; o++)
                    facc[o] = fmaf(h[q], w3s[k*TOUT_ + ob + o], facc[o]);
            }
        }
        const float4* er = (const float4*)&Es[row * ES_P];
#pragma unroll 4
        for (int k4 = 0; k4 < H_/4; k4++) {
            float4 ev = er[k4];
            float e4[4] = {ev.x, ev.y, ev.z, ev.w};
#pragma unroll
            for (int q = 0; q < 4; q++) {
                int k = k4*4 + q;
#pragma unroll
                for (int o = 0; o < 6; o++)
                    facc[o] = fmaf(e4[q], pjs[k*TOUT_ + ob + o], facc[o]);
            }
        }

        const int gm = m0 + row;
        const int b = gm / N_, n = gm % N_;
#pragma unroll
        for (int o = 0; o < 6; o++) {
            int oo = ob + o;
            float c = (facc[o] - dbnm[oo]) * rsqrtf(dbnv[oo] + BN_EPS_) * dbng[oo] + dbnb[oo];
            out[((size_t)(b*TOUT_ + oo))*N_ + n] = c;
        }
    }
}

// ---------------- host launch ----------------
extern "C" void kernel_launch(void* const* d_in, const int* in_sizes, int n_in,
                              void* d_out, int out_size)
{
    const float* x        = (const float*)d_in[0];
    const float* W1       = (const float*)d_in[1];
    const float* W2       = (const float*)d_in[2];
    const float* enc_w1   = (const float*)d_in[3];
    const float* enc_b1   = (const float*)d_in[4];
    const float* enc_w2   = (const float*)d_in[5];
    const float* enc_b2   = (const float*)d_in[6];
    const float* enc_w3   = (const float*)d_in[7];
    const float* enc_b3   = (const float*)d_in[8];
    const float* enc_proj = (const float*)d_in[9];
    const float* enc_bn_g = (const float*)d_in[10];
    const float* enc_bn_b = (const float*)d_in[11];
    const float* enc_bn_m = (const float*)d_in[12];
    const float* enc_bn_v = (const float*)d_in[13];
    const float* dec_w1   = (const float*)d_in[14];
    const float* dec_b1   = (const float*)d_in[15];
    const float* dec_w2   = (const float*)d_in[16];
    const float* dec_b2   = (const float*)d_in[17];
    const float* dec_w3   = (const float*)d_in[18];
    const float* dec_b3   = (const float*)d_in[19];
    const float* dec_proj = (const float*)d_in[20];
    const float* dec_bn_g = (const float*)d_in[21];
    const float* dec_bn_b = (const float*)d_in[22];
    const float* dec_bn_m = (const float*)d_in[23];
    const float* dec_bn_v = (const float*)d_in[24];
    float* out = (float*)d_out;

    static int attr_done = 0;
    if (!attr_done) {
        cudaFuncSetAttribute(k_graph_mma, cudaFuncAttributeMaxDynamicSharedMemorySize, SG_BYTES);
        cudaFuncSetAttribute(k_pair_mma,  cudaFuncAttributeMaxDynamicSharedMemorySize, PIPE2_B);
        cudaFuncSetAttribute(k_chain,     cudaFuncAttributeMaxDynamicSharedMemorySize, CHAIN_BYTES);
        attr_done = 1;
    }

    // 5 launches total
    k_softprep  <<<((HID2_+H_)*TH_ + 49152 + 255)/256, 256>>>(
        x, enc_w1, enc_proj, enc_w2, enc_w3, dec_w1, dec_w2);            // 1
    k_graph_mma <<<dim3(N_/128, N_/128, B_), 256, SG_BYTES>>>(x);        // 2
    k_buildz    <<<(M_*TH_/8)/256, 256>>>(x, W1, W2);                    // 3
    k_pair_mma  <<<dim3(M_/128, 3), 256, PIPE2_B>>>(enc_b1);             // 4
    k_chain     <<<M_/128, 256, CHAIN_BYTES>>>(enc_b2, enc_b3,
        enc_bn_g, enc_bn_b, enc_bn_m, enc_bn_v, dec_b1, dec_b2,
        dec_w3, dec_b3, dec_proj,
        dec_bn_g, dec_bn_b, dec_bn_m, dec_bn_v, out);                    // 5
}